// round 2
// baseline (speedup 1.0000x reference)
#include <cuda_runtime.h>

#define NS    512
#define NOBJ  16
#define MPTS  8192
#define HW    16384      // 128*128
#define HW4   (HW / 4)
#define TPB   256

// Fused scoring kernel.
// blocks [0, NS)        : pv  (masked projected distance over ROI pixels)  -- memory bound
// blocks [NS, 2*NS)     : re/te/ad/pj (per-sample scalars + mesh reductions) -- compute/L2 bound
__global__ __launch_bounds__(TPB) void score_kernel(
    const int*   __restrict__ obj_id,
    const float* __restrict__ cam_K,     // [NS,3,3]
    const float* __restrict__ gtR,       // [NS,3,3]
    const float* __restrict__ gtT,       // [NS,3]
    const float* __restrict__ prR,       // [NS,3,3]
    const float* __restrict__ prT,       // [NS,3]
    const float* __restrict__ coord,     // [NS,3,H,W]
    const unsigned int* __restrict__ maskp, // [NS,H,W] (f32 or i32 bits; nonzero == true)
    const float* __restrict__ mesh,      // [NOBJ,MPTS,3]
    const float* __restrict__ diam,      // [NOBJ]
    float*       __restrict__ out)       // [5,NS]
{
    const int tid  = threadIdx.x;
    const bool is_pv = (blockIdx.x < NS);
    const int n   = is_pv ? blockIdx.x : (blockIdx.x - NS);

    __shared__ float sKp[9], sKg[9], sktp[3], sktg[3];
    __shared__ float sdR[9], sdt[3];
    __shared__ float sInvDiam;
    __shared__ int   sObj;
    __shared__ float redA[8], redB[8];

    if (tid == 0) {
        float K[9], Rp[9], Rg[9], tp[3], tg[3];
#pragma unroll
        for (int k = 0; k < 9; k++) {
            K[k]  = cam_K[n * 9 + k];
            Rp[k] = prR[n * 9 + k];
            Rg[k] = gtR[n * 9 + k];
        }
#pragma unroll
        for (int k = 0; k < 3; k++) {
            tp[k] = prT[n * 3 + k];
            tg[k] = gtT[n * 3 + k];
        }
        // Kp = K @ Rp, Kg = K @ Rg, ktp = K @ tp, ktg = K @ tg
#pragma unroll
        for (int i = 0; i < 3; i++) {
#pragma unroll
            for (int j = 0; j < 3; j++) {
                sKp[i * 3 + j] = K[i*3+0]*Rp[0*3+j] + K[i*3+1]*Rp[1*3+j] + K[i*3+2]*Rp[2*3+j];
                sKg[i * 3 + j] = K[i*3+0]*Rg[0*3+j] + K[i*3+1]*Rg[1*3+j] + K[i*3+2]*Rg[2*3+j];
            }
            sktp[i] = K[i*3+0]*tp[0] + K[i*3+1]*tp[1] + K[i*3+2]*tp[2];
            sktg[i] = K[i*3+0]*tg[0] + K[i*3+1]*tg[1] + K[i*3+2]*tg[2];
        }
        if (!is_pv) {
#pragma unroll
            for (int k = 0; k < 9; k++) sdR[k] = Rp[k] - Rg[k];
#pragma unroll
            for (int k = 0; k < 3; k++) sdt[k] = tp[k] - tg[k];
            int obj = obj_id[n];
            sObj = obj;
            sInvDiam = 1.0f / diam[obj];
            // RE (degrees):  trace(Rp Rg^T) = sum_ij Rp_ij * Rg_ij
            float tr = 0.0f;
#pragma unroll
            for (int k = 0; k < 9; k++) tr += Rp[k] * Rg[k];
            float c = fminf(fmaxf(tr, -1.0f), 3.0f);
            out[n] = acosf((c - 1.0f) * 0.5f) * 57.2957795130823209f;
            // TE (cm)
            float dx = tp[0] - tg[0], dy = tp[1] - tg[1], dz = tp[2] - tg[2];
            out[NS + n] = sqrtf(dx*dx + dy*dy + dz*dz) * 100.0f;
        }
    }
    __syncthreads();

    float accA = 0.0f, accB = 0.0f;

    if (is_pv) {
        const float4* vx = (const float4*)(coord + (size_t)n * 3 * HW);
        const float4* vy = vx + HW4;
        const float4* vz = vy + HW4;
        const uint4*  mk = (const uint4*)(maskp + (size_t)n * HW);
        for (int i = tid; i < HW4; i += TPB) {
            float4 X = __ldg(vx + i);
            float4 Y = __ldg(vy + i);
            float4 Z = __ldg(vz + i);
            uint4  Mw = __ldg(mk + i);
            float xs[4] = {X.x, X.y, X.z, X.w};
            float ys[4] = {Y.x, Y.y, Y.z, Y.w};
            float zs[4] = {Z.x, Z.y, Z.z, Z.w};
            unsigned int ms[4] = {Mw.x, Mw.y, Mw.z, Mw.w};
#pragma unroll
            for (int j = 0; j < 4; j++) {
                float x = xs[j], y = ys[j], z = zs[j];
                float hx = sKp[0]*x + sKp[1]*y + sKp[2]*z + sktp[0];
                float hy = sKp[3]*x + sKp[4]*y + sKp[5]*z + sktp[1];
                float hz = sKp[6]*x + sKp[7]*y + sKp[8]*z + sktp[2];
                float gx = sKg[0]*x + sKg[1]*y + sKg[2]*z + sktg[0];
                float gy = sKg[3]*x + sKg[4]*y + sKg[5]*z + sktg[1];
                float gz = sKg[6]*x + sKg[7]*y + sKg[8]*z + sktg[2];
                float izp = 1.0f / hz;
                float izg = 1.0f / gz;
                float ux = hx * izp - gx * izg;
                float uy = hy * izp - gy * izg;
                float d  = sqrtf(ux*ux + uy*uy);
                if (ms[j] != 0u) { accA += d; accB += 1.0f; }
            }
        }
    } else {
        const float* pts = mesh + (size_t)sObj * MPTS * 3;
        for (int m = tid; m < MPTS; m += TPB) {
            float px = pts[m * 3 + 0];
            float py = pts[m * 3 + 1];
            float pz = pts[m * 3 + 2];
            // ADD
            float ax = sdR[0]*px + sdR[1]*py + sdR[2]*pz + sdt[0];
            float ay = sdR[3]*px + sdR[4]*py + sdR[5]*pz + sdt[1];
            float az = sdR[6]*px + sdR[7]*py + sdR[8]*pz + sdt[2];
            accA += sqrtf(ax*ax + ay*ay + az*az);
            // PROJ
            float hx = sKp[0]*px + sKp[1]*py + sKp[2]*pz + sktp[0];
            float hy = sKp[3]*px + sKp[4]*py + sKp[5]*pz + sktp[1];
            float hz = sKp[6]*px + sKp[7]*py + sKp[8]*pz + sktp[2];
            float gx = sKg[0]*px + sKg[1]*py + sKg[2]*pz + sktg[0];
            float gy = sKg[3]*px + sKg[4]*py + sKg[5]*pz + sktg[1];
            float gz = sKg[6]*px + sKg[7]*py + sKg[8]*pz + sktg[2];
            float izp = 1.0f / hz;
            float izg = 1.0f / gz;
            float ux = hx * izp - gx * izg;
            float uy = hy * izp - gy * izg;
            accB += sqrtf(ux*ux + uy*uy);
        }
    }

    // block reduce (accA, accB)
    {
        const int lane = tid & 31;
        const int wid  = tid >> 5;
#pragma unroll
        for (int o = 16; o > 0; o >>= 1) {
            accA += __shfl_down_sync(0xffffffffu, accA, o);
            accB += __shfl_down_sync(0xffffffffu, accB, o);
        }
        if (lane == 0) { redA[wid] = accA; redB[wid] = accB; }
        __syncthreads();
        if (wid == 0) {
            accA = (lane < (TPB / 32)) ? redA[lane] : 0.0f;
            accB = (lane < (TPB / 32)) ? redB[lane] : 0.0f;
#pragma unroll
            for (int o = 4; o > 0; o >>= 1) {
                accA += __shfl_down_sync(0xffffffffu, accA, o);
                accB += __shfl_down_sync(0xffffffffu, accB, o);
            }
            if (lane == 0) {
                if (is_pv) {
                    out[4 * NS + n] = accA / fmaxf(accB, 1.0f);
                } else {
                    out[2 * NS + n] = accA * (1.0f / MPTS) * sInvDiam;
                    out[3 * NS + n] = accB * (1.0f / MPTS);
                }
            }
        }
    }
}

extern "C" void kernel_launch(void* const* d_in, const int* in_sizes, int n_in,
                              void* d_out, int out_size) {
    const int*   obj_id = (const int*)  d_in[0];
    const float* cam_K  = (const float*)d_in[1];
    const float* gtR    = (const float*)d_in[2];
    const float* gtT    = (const float*)d_in[3];
    const float* prR    = (const float*)d_in[4];
    const float* prT    = (const float*)d_in[5];
    const float* coord  = (const float*)d_in[6];
    const unsigned int* maskp = (const unsigned int*)d_in[7];
    const float* mesh   = (const float*)d_in[8];
    const float* diam   = (const float*)d_in[9];
    float* out = (float*)d_out;

    score_kernel<<<2 * NS, TPB>>>(obj_id, cam_K, gtR, gtT, prR, prT,
                                  coord, maskp, mesh, diam, out);
}

// round 3
// speedup vs baseline: 1.1593x; 1.1593x over previous
#include <cuda_runtime.h>

#define NS    512
#define NOBJ  16
#define MPTS  8192
#define HW    16384      // 128*128
#define HW4   (HW / 4)
#define TPB   256

typedef unsigned long long u64;

__device__ __forceinline__ u64 pk2(float lo, float hi) {
    u64 r; asm("mov.b64 %0, {%1, %2};" : "=l"(r) : "f"(lo), "f"(hi)); return r;
}
__device__ __forceinline__ void upk2(u64 v, float& lo, float& hi) {
    asm("mov.b64 {%0, %1}, %2;" : "=f"(lo), "=f"(hi) : "l"(v));
}
__device__ __forceinline__ u64 fma2(u64 a, u64 b, u64 c) {
    u64 d; asm("fma.rn.f32x2 %0, %1, %2, %3;" : "=l"(d) : "l"(a), "l"(b), "l"(c)); return d;
}
__device__ __forceinline__ u64 mul2(u64 a, u64 b) {
    u64 d; asm("mul.rn.f32x2 %0, %1, %2;" : "=l"(d) : "l"(a), "l"(b)); return d;
}
__device__ __forceinline__ float rcpa(float x) {
    float r; asm("rcp.approx.f32 %0, %1;" : "=f"(r) : "f"(x)); return r;
}
__device__ __forceinline__ float sqrta(float x) {
    float r; asm("sqrt.approx.f32 %0, %1;" : "=f"(r) : "f"(x)); return r;
}

// Fused scoring kernel.
// blocks [0, NS)     : pv  (masked projected distance over ROI pixels) -- memory bound
// blocks [NS, 2*NS)  : re/te/ad/pj (scalars + mesh reductions)         -- compute bound
__global__ __launch_bounds__(TPB) void score_kernel(
    const int*   __restrict__ obj_id,
    const float* __restrict__ cam_K,
    const float* __restrict__ gtR,
    const float* __restrict__ gtT,
    const float* __restrict__ prR,
    const float* __restrict__ prT,
    const float* __restrict__ coord,     // [NS,3,H,W]
    const unsigned int* __restrict__ maskp, // [NS,H,W] nonzero == true
    const float* __restrict__ mesh,      // [NOBJ,MPTS,3]
    const float* __restrict__ diam,
    float*       __restrict__ out)       // [5,NS]
{
    const int tid  = threadIdx.x;
    const bool is_pv = (blockIdx.x < NS);
    const int n   = is_pv ? blockIdx.x : (blockIdx.x - NS);

    // packed (broadcast) coefficients
    __shared__ u64 sKp[9], sKg[9], sktp[3], sktg[3];
    __shared__ u64 sdR[9], sdt[3];
    __shared__ float sInvDiam;
    __shared__ int   sObj;
    __shared__ float redA[8], redB[8];

    if (tid == 0) {
        float K[9], Rp[9], Rg[9], tp[3], tg[3];
#pragma unroll
        for (int k = 0; k < 9; k++) {
            K[k]  = cam_K[n * 9 + k];
            Rp[k] = prR[n * 9 + k];
            Rg[k] = gtR[n * 9 + k];
        }
#pragma unroll
        for (int k = 0; k < 3; k++) { tp[k] = prT[n * 3 + k]; tg[k] = gtT[n * 3 + k]; }
#pragma unroll
        for (int i = 0; i < 3; i++) {
#pragma unroll
            for (int j = 0; j < 3; j++) {
                float a = K[i*3+0]*Rp[0*3+j] + K[i*3+1]*Rp[1*3+j] + K[i*3+2]*Rp[2*3+j];
                float b = K[i*3+0]*Rg[0*3+j] + K[i*3+1]*Rg[1*3+j] + K[i*3+2]*Rg[2*3+j];
                sKp[i*3+j] = pk2(a, a);
                sKg[i*3+j] = pk2(b, b);
            }
            float a = K[i*3+0]*tp[0] + K[i*3+1]*tp[1] + K[i*3+2]*tp[2];
            float b = K[i*3+0]*tg[0] + K[i*3+1]*tg[1] + K[i*3+2]*tg[2];
            sktp[i] = pk2(a, a);
            sktg[i] = pk2(b, b);
        }
        if (!is_pv) {
#pragma unroll
            for (int k = 0; k < 9; k++) { float d = Rp[k] - Rg[k]; sdR[k] = pk2(d, d); }
#pragma unroll
            for (int k = 0; k < 3; k++) { float d = tp[k] - tg[k]; sdt[k] = pk2(d, d); }
            int obj = obj_id[n];
            sObj = obj;
            sInvDiam = 1.0f / diam[obj];
            float tr = 0.0f;
#pragma unroll
            for (int k = 0; k < 9; k++) tr += Rp[k] * Rg[k];
            float c = fminf(fmaxf(tr, -1.0f), 3.0f);
            out[n] = acosf((c - 1.0f) * 0.5f) * 57.2957795130823209f;
            float dx = tp[0]-tg[0], dy = tp[1]-tg[1], dz = tp[2]-tg[2];
            out[NS + n] = sqrtf(dx*dx + dy*dy + dz*dz) * 100.0f;
        }
    }
    __syncthreads();

    float accA = 0.0f, accB = 0.0f;

    if (is_pv) {
        const float4* vx = (const float4*)(coord + (size_t)n * 3 * HW);
        const float4* vy = vx + HW4;
        const float4* vz = vy + HW4;
        const uint4*  mk = (const uint4*)(maskp + (size_t)n * HW);
        for (int i = tid; i < HW4; i += TPB) {
            float4 X = __ldg(vx + i);
            float4 Y = __ldg(vy + i);
            float4 Z = __ldg(vz + i);
            uint4  Mw = __ldg(mk + i);
#pragma unroll
            for (int half = 0; half < 2; half++) {
                u64 x2 = half ? pk2(X.z, X.w) : pk2(X.x, X.y);
                u64 y2 = half ? pk2(Y.z, Y.w) : pk2(Y.x, Y.y);
                u64 z2 = half ? pk2(Z.z, Z.w) : pk2(Z.x, Z.y);
                unsigned int m0 = half ? Mw.z : Mw.x;
                unsigned int m1 = half ? Mw.w : Mw.y;

                u64 hx = fma2(sKp[0], x2, fma2(sKp[1], y2, fma2(sKp[2], z2, sktp[0])));
                u64 hy = fma2(sKp[3], x2, fma2(sKp[4], y2, fma2(sKp[5], z2, sktp[1])));
                u64 hz = fma2(sKp[6], x2, fma2(sKp[7], y2, fma2(sKp[8], z2, sktp[2])));
                u64 gx = fma2(sKg[0], x2, fma2(sKg[1], y2, fma2(sKg[2], z2, sktg[0])));
                u64 gy = fma2(sKg[3], x2, fma2(sKg[4], y2, fma2(sKg[5], z2, sktg[1])));
                u64 gz = fma2(sKg[6], x2, fma2(sKg[7], y2, fma2(sKg[8], z2, sktg[2])));

                float hz0, hz1, gz0, gz1;
                upk2(hz, hz0, hz1);
                upk2(gz, gz0, gz1);
                u64 ip2  = pk2(rcpa(hz0),  rcpa(hz1));   // 1/hz
                u64 ign2 = pk2(rcpa(-gz0), rcpa(-gz1));  // -1/gz

                u64 ux = fma2(gx, ign2, mul2(hx, ip2));
                u64 uy = fma2(gy, ign2, mul2(hy, ip2));
                u64 s2 = fma2(uy, uy, mul2(ux, ux));
                float s0, s1;
                upk2(s2, s0, s1);
                if (m0 != 0u) { accA += sqrta(s0); accB += 1.0f; }
                if (m1 != 0u) { accA += sqrta(s1); accB += 1.0f; }
            }
        }
    } else {
        const float2* pts2 = (const float2*)(mesh + (size_t)sObj * MPTS * 3);
        // pairs of points: pair t covers points 2t, 2t+1 -> float2 indices 3t..3t+2
        for (int t = tid; t < MPTS / 2; t += TPB) {
            float2 a = __ldg(pts2 + 3*t + 0);   // v0 v1
            float2 b = __ldg(pts2 + 3*t + 1);   // v2 v3
            float2 c = __ldg(pts2 + 3*t + 2);   // v4 v5
            u64 px2 = pk2(a.x, b.y);
            u64 py2 = pk2(a.y, c.x);
            u64 pz2 = pk2(b.x, c.y);

            // ADD
            u64 ax = fma2(sdR[0], px2, fma2(sdR[1], py2, fma2(sdR[2], pz2, sdt[0])));
            u64 ay = fma2(sdR[3], px2, fma2(sdR[4], py2, fma2(sdR[5], pz2, sdt[1])));
            u64 az = fma2(sdR[6], px2, fma2(sdR[7], py2, fma2(sdR[8], pz2, sdt[2])));
            u64 sa = fma2(az, az, fma2(ay, ay, mul2(ax, ax)));
            float sa0, sa1;
            upk2(sa, sa0, sa1);
            accA += sqrta(sa0) + sqrta(sa1);

            // PROJ
            u64 hx = fma2(sKp[0], px2, fma2(sKp[1], py2, fma2(sKp[2], pz2, sktp[0])));
            u64 hy = fma2(sKp[3], px2, fma2(sKp[4], py2, fma2(sKp[5], pz2, sktp[1])));
            u64 hz = fma2(sKp[6], px2, fma2(sKp[7], py2, fma2(sKp[8], pz2, sktp[2])));
            u64 gx = fma2(sKg[0], px2, fma2(sKg[1], py2, fma2(sKg[2], pz2, sktg[0])));
            u64 gy = fma2(sKg[3], px2, fma2(sKg[4], py2, fma2(sKg[5], pz2, sktg[1])));
            u64 gz = fma2(sKg[6], px2, fma2(sKg[7], py2, fma2(sKg[8], pz2, sktg[2])));
            float hz0, hz1, gz0, gz1;
            upk2(hz, hz0, hz1);
            upk2(gz, gz0, gz1);
            u64 ip2  = pk2(rcpa(hz0),  rcpa(hz1));
            u64 ign2 = pk2(rcpa(-gz0), rcpa(-gz1));
            u64 ux = fma2(gx, ign2, mul2(hx, ip2));
            u64 uy = fma2(gy, ign2, mul2(hy, ip2));
            u64 sp = fma2(uy, uy, mul2(ux, ux));
            float sp0, sp1;
            upk2(sp, sp0, sp1);
            accB += sqrta(sp0) + sqrta(sp1);
        }
    }

    // block reduce (accA, accB)
    {
        const int lane = tid & 31;
        const int wid  = tid >> 5;
#pragma unroll
        for (int o = 16; o > 0; o >>= 1) {
            accA += __shfl_down_sync(0xffffffffu, accA, o);
            accB += __shfl_down_sync(0xffffffffu, accB, o);
        }
        if (lane == 0) { redA[wid] = accA; redB[wid] = accB; }
        __syncthreads();
        if (wid == 0) {
            accA = (lane < (TPB / 32)) ? redA[lane] : 0.0f;
            accB = (lane < (TPB / 32)) ? redB[lane] : 0.0f;
#pragma unroll
            for (int o = 4; o > 0; o >>= 1) {
                accA += __shfl_down_sync(0xffffffffu, accA, o);
                accB += __shfl_down_sync(0xffffffffu, accB, o);
            }
            if (lane == 0) {
                if (is_pv) {
                    out[4 * NS + n] = accA / fmaxf(accB, 1.0f);
                } else {
                    out[2 * NS + n] = accA * (1.0f / MPTS) * sInvDiam;
                    out[3 * NS + n] = accB * (1.0f / MPTS);
                }
            }
        }
    }
}

extern "C" void kernel_launch(void* const* d_in, const int* in_sizes, int n_in,
                              void* d_out, int out_size) {
    const int*   obj_id = (const int*)  d_in[0];
    const float* cam_K  = (const float*)d_in[1];
    const float* gtR    = (const float*)d_in[2];
    const float* gtT    = (const float*)d_in[3];
    const float* prR    = (const float*)d_in[4];
    const float* prT    = (const float*)d_in[5];
    const float* coord  = (const float*)d_in[6];
    const unsigned int* maskp = (const unsigned int*)d_in[7];
    const float* mesh   = (const float*)d_in[8];
    const float* diam   = (const float*)d_in[9];
    float* out = (float*)d_out;

    score_kernel<<<2 * NS, TPB>>>(obj_id, cam_K, gtR, gtT, prR, prT,
                                  coord, maskp, mesh, diam, out);
}

// round 4
// speedup vs baseline: 1.4505x; 1.2511x over previous
#include <cuda_runtime.h>

#define NS    512
#define NOBJ  16
#define MPTS  8192
#define HW    16384      // 128*128
#define HW4   (HW / 4)
#define TPB   256

typedef unsigned long long u64;

__device__ __forceinline__ u64 pk2(float lo, float hi) {
    u64 r; asm("mov.b64 %0, {%1, %2};" : "=l"(r) : "f"(lo), "f"(hi)); return r;
}
__device__ __forceinline__ void upk2(u64 v, float& lo, float& hi) {
    asm("mov.b64 {%0, %1}, %2;" : "=f"(lo), "=f"(hi) : "l"(v));
}
__device__ __forceinline__ u64 fma2(u64 a, u64 b, u64 c) {
    u64 d; asm("fma.rn.f32x2 %0, %1, %2, %3;" : "=l"(d) : "l"(a), "l"(b), "l"(c)); return d;
}
__device__ __forceinline__ u64 mul2(u64 a, u64 b) {
    u64 d; asm("mul.rn.f32x2 %0, %1, %2;" : "=l"(d) : "l"(a), "l"(b)); return d;
}
__device__ __forceinline__ float rcpa(float x) {
    float r; asm("rcp.approx.f32 %0, %1;" : "=f"(r) : "f"(x)); return r;
}
__device__ __forceinline__ float sqrta(float x) {
    float r; asm("sqrt.approx.f32 %0, %1;" : "=f"(r) : "f"(x)); return r;
}

// blocks [0, NS)     : pv  (masked projected distance over ROI)  -- memory/issue bound
// blocks [NS, 2*NS)  : re/te/ad/pj (scalars + mesh reductions)   -- fma bound
__global__ __launch_bounds__(TPB, 2) void score_kernel(
    const int*   __restrict__ obj_id,
    const float* __restrict__ cam_K,
    const float* __restrict__ gtR,
    const float* __restrict__ gtT,
    const float* __restrict__ prR,
    const float* __restrict__ prT,
    const float* __restrict__ coord,        // [NS,3,H,W]
    const unsigned int* __restrict__ maskp, // [NS,H,W] nonzero == true
    const float* __restrict__ mesh,         // [NOBJ,MPTS,3]
    const float* __restrict__ diam,
    float*       __restrict__ out)          // [5,NS]
{
    const int tid  = threadIdx.x;
    const bool is_pv = (blockIdx.x < NS);
    const int n   = is_pv ? blockIdx.x : (blockIdx.x - NS);

    __shared__ u64 sdR[9], sdt[3];
    __shared__ float sInvDiam;
    __shared__ int   sObj;
    __shared__ float redA[8], redB[8];

    // ---- per-thread register coefficients (broadcast pairs) ----
    // Kp = K@Rp rows 0..2 ; Kg rows 0,1 NEGATED, row 2 positive.
    float K[9], Rp[9], Rg[9], tp[3], tg[3];
#pragma unroll
    for (int k = 0; k < 9; k++) {
        K[k]  = __ldg(cam_K + n * 9 + k);
        Rp[k] = __ldg(prR   + n * 9 + k);
        Rg[k] = __ldg(gtR   + n * 9 + k);
    }
#pragma unroll
    for (int k = 0; k < 3; k++) { tp[k] = __ldg(prT + n*3 + k); tg[k] = __ldg(gtT + n*3 + k); }

    u64 cKp[9], cKg[9], cktp[3], cktg[3];
#pragma unroll
    for (int i = 0; i < 3; i++) {
        float sg = (i < 2) ? -1.0f : 1.0f;   // negate Kg rows 0,1
#pragma unroll
        for (int j = 0; j < 3; j++) {
            float a = K[i*3+0]*Rp[0*3+j] + K[i*3+1]*Rp[1*3+j] + K[i*3+2]*Rp[2*3+j];
            float b = (K[i*3+0]*Rg[0*3+j] + K[i*3+1]*Rg[1*3+j] + K[i*3+2]*Rg[2*3+j]) * sg;
            cKp[i*3+j] = pk2(a, a);
            cKg[i*3+j] = pk2(b, b);
        }
        float a = K[i*3+0]*tp[0] + K[i*3+1]*tp[1] + K[i*3+2]*tp[2];
        float b = (K[i*3+0]*tg[0] + K[i*3+1]*tg[1] + K[i*3+2]*tg[2]) * sg;
        cktp[i] = pk2(a, a);
        cktg[i] = pk2(b, b);
    }

    if (!is_pv && tid == 0) {
#pragma unroll
        for (int k = 0; k < 9; k++) { float d = Rp[k] - Rg[k]; sdR[k] = pk2(d, d); }
#pragma unroll
        for (int k = 0; k < 3; k++) { float d = tp[k] - tg[k]; sdt[k] = pk2(d, d); }
        int obj = obj_id[n];
        sObj = obj;
        sInvDiam = 1.0f / diam[obj];
        float tr = 0.0f;
#pragma unroll
        for (int k = 0; k < 9; k++) tr += Rp[k] * Rg[k];
        float c = fminf(fmaxf(tr, -1.0f), 3.0f);
        out[n] = acosf((c - 1.0f) * 0.5f) * 57.2957795130823209f;
        float dx = tp[0]-tg[0], dy = tp[1]-tg[1], dz = tp[2]-tg[2];
        out[NS + n] = sqrtf(dx*dx + dy*dy + dz*dz) * 100.0f;
    }
    if (!is_pv) __syncthreads();

    float accA = 0.0f, accB = 0.0f;

    if (is_pv) {
        const float4* vx = (const float4*)(coord + (size_t)n * 3 * HW);
        const float4* vy = vx + HW4;
        const float4* vz = vy + HW4;
        const uint4*  mk = (const uint4*)(maskp + (size_t)n * HW);
        for (int i = tid; i < HW4; i += TPB) {
            float4 X = __ldg(vx + i);
            float4 Y = __ldg(vy + i);
            float4 Z = __ldg(vz + i);
            uint4  Mw = __ldg(mk + i);
#pragma unroll
            for (int half = 0; half < 2; half++) {
                u64 x2 = half ? pk2(X.z, X.w) : pk2(X.x, X.y);
                u64 y2 = half ? pk2(Y.z, Y.w) : pk2(Y.x, Y.y);
                u64 z2 = half ? pk2(Z.z, Z.w) : pk2(Z.x, Z.y);
                unsigned int m0 = half ? Mw.z : Mw.x;
                unsigned int m1 = half ? Mw.w : Mw.y;

                u64 hx  = fma2(cKp[0], x2, fma2(cKp[1], y2, fma2(cKp[2], z2, cktp[0])));
                u64 hy  = fma2(cKp[3], x2, fma2(cKp[4], y2, fma2(cKp[5], z2, cktp[1])));
                u64 hz  = fma2(cKp[6], x2, fma2(cKp[7], y2, fma2(cKp[8], z2, cktp[2])));
                u64 gxn = fma2(cKg[0], x2, fma2(cKg[1], y2, fma2(cKg[2], z2, cktg[0]))); // -gx
                u64 gyn = fma2(cKg[3], x2, fma2(cKg[4], y2, fma2(cKg[5], z2, cktg[1]))); // -gy
                u64 gz  = fma2(cKg[6], x2, fma2(cKg[7], y2, fma2(cKg[8], z2, cktg[2])));

                u64 nx = fma2(gxn, hz, mul2(hx, gz));   // hx*gz - gx*hz
                u64 ny = fma2(gyn, hz, mul2(hy, gz));
                u64 dn = mul2(hz, gz);
                float dn0, dn1;
                upk2(dn, dn0, dn1);
                u64 r2 = pk2(rcpa(dn0), rcpa(dn1));
                u64 s2 = mul2(fma2(ny, ny, mul2(nx, nx)), mul2(r2, r2));
                float s0, s1;
                upk2(s2, s0, s1);
                if (m0 != 0u) { accA += sqrta(s0); accB += 1.0f; }
                if (m1 != 0u) { accA += sqrta(s1); accB += 1.0f; }
            }
        }
    } else {
        const float2* pts2 = (const float2*)(mesh + (size_t)sObj * MPTS * 3);
        for (int t = tid; t < MPTS / 2; t += TPB) {
            float2 a = __ldg(pts2 + 3*t + 0);
            float2 b = __ldg(pts2 + 3*t + 1);
            float2 c = __ldg(pts2 + 3*t + 2);
            u64 px2 = pk2(a.x, b.y);
            u64 py2 = pk2(a.y, c.x);
            u64 pz2 = pk2(b.x, c.y);

            // ADD
            u64 ax = fma2(sdR[0], px2, fma2(sdR[1], py2, fma2(sdR[2], pz2, sdt[0])));
            u64 ay = fma2(sdR[3], px2, fma2(sdR[4], py2, fma2(sdR[5], pz2, sdt[1])));
            u64 az = fma2(sdR[6], px2, fma2(sdR[7], py2, fma2(sdR[8], pz2, sdt[2])));
            u64 sa = fma2(az, az, fma2(ay, ay, mul2(ax, ax)));
            float sa0, sa1;
            upk2(sa, sa0, sa1);
            accA += sqrta(sa0) + sqrta(sa1);

            // PROJ
            u64 hx  = fma2(cKp[0], px2, fma2(cKp[1], py2, fma2(cKp[2], pz2, cktp[0])));
            u64 hy  = fma2(cKp[3], px2, fma2(cKp[4], py2, fma2(cKp[5], pz2, cktp[1])));
            u64 hz  = fma2(cKp[6], px2, fma2(cKp[7], py2, fma2(cKp[8], pz2, cktp[2])));
            u64 gxn = fma2(cKg[0], px2, fma2(cKg[1], py2, fma2(cKg[2], pz2, cktg[0])));
            u64 gyn = fma2(cKg[3], px2, fma2(cKg[4], py2, fma2(cKg[5], pz2, cktg[1])));
            u64 gz  = fma2(cKg[6], px2, fma2(cKg[7], py2, fma2(cKg[8], pz2, cktg[2])));

            u64 nx = fma2(gxn, hz, mul2(hx, gz));
            u64 ny = fma2(gyn, hz, mul2(hy, gz));
            u64 dn = mul2(hz, gz);
            float dn0, dn1;
            upk2(dn, dn0, dn1);
            u64 r2 = pk2(rcpa(dn0), rcpa(dn1));
            u64 sp = mul2(fma2(ny, ny, mul2(nx, nx)), mul2(r2, r2));
            float sp0, sp1;
            upk2(sp, sp0, sp1);
            accB += sqrta(sp0) + sqrta(sp1);
        }
    }

    // block reduce (accA, accB)
    {
        const int lane = tid & 31;
        const int wid  = tid >> 5;
#pragma unroll
        for (int o = 16; o > 0; o >>= 1) {
            accA += __shfl_down_sync(0xffffffffu, accA, o);
            accB += __shfl_down_sync(0xffffffffu, accB, o);
        }
        if (lane == 0) { redA[wid] = accA; redB[wid] = accB; }
        __syncthreads();
        if (wid == 0) {
            accA = (lane < (TPB / 32)) ? redA[lane] : 0.0f;
            accB = (lane < (TPB / 32)) ? redB[lane] : 0.0f;
#pragma unroll
            for (int o = 4; o > 0; o >>= 1) {
                accA += __shfl_down_sync(0xffffffffu, accA, o);
                accB += __shfl_down_sync(0xffffffffu, accB, o);
            }
            if (lane == 0) {
                if (is_pv) {
                    out[4 * NS + n] = accA / fmaxf(accB, 1.0f);
                } else {
                    out[2 * NS + n] = accA * (1.0f / MPTS) * sInvDiam;
                    out[3 * NS + n] = accB * (1.0f / MPTS);
                }
            }
        }
    }
}

extern "C" void kernel_launch(void* const* d_in, const int* in_sizes, int n_in,
                              void* d_out, int out_size) {
    const int*   obj_id = (const int*)  d_in[0];
    const float* cam_K  = (const float*)d_in[1];
    const float* gtR    = (const float*)d_in[2];
    const float* gtT    = (const float*)d_in[3];
    const float* prR    = (const float*)d_in[4];
    const float* prT    = (const float*)d_in[5];
    const float* coord  = (const float*)d_in[6];
    const unsigned int* maskp = (const unsigned int*)d_in[7];
    const float* mesh   = (const float*)d_in[8];
    const float* diam   = (const float*)d_in[9];
    float* out = (float*)d_out;

    score_kernel<<<2 * NS, TPB>>>(obj_id, cam_K, gtR, gtT, prR, prT,
                                  coord, maskp, mesh, diam, out);
}

// round 5
// speedup vs baseline: 1.7494x; 1.2061x over previous
#include <cuda_runtime.h>

#define NS    512
#define NOBJ  16
#define MPTS  8192
#define HW    16384      // 128*128
#define HW4   (HW / 4)
#define TPB   256

typedef unsigned long long u64;

__device__ __forceinline__ u64 pk2(float lo, float hi) {
    u64 r; asm("mov.b64 %0, {%1, %2};" : "=l"(r) : "f"(lo), "f"(hi)); return r;
}
__device__ __forceinline__ void upk2(u64 v, float& lo, float& hi) {
    asm("mov.b64 {%0, %1}, %2;" : "=f"(lo), "=f"(hi) : "l"(v));
}
__device__ __forceinline__ u64 fma2(u64 a, u64 b, u64 c) {
    u64 d; asm("fma.rn.f32x2 %0, %1, %2, %3;" : "=l"(d) : "l"(a), "l"(b), "l"(c)); return d;
}
__device__ __forceinline__ u64 mul2(u64 a, u64 b) {
    u64 d; asm("mul.rn.f32x2 %0, %1, %2;" : "=l"(d) : "l"(a), "l"(b)); return d;
}
__device__ __forceinline__ float rcpa(float x) {
    float r; asm("rcp.approx.f32 %0, %1;" : "=f"(r) : "f"(x)); return r;
}
__device__ __forceinline__ float sqrta(float x) {
    float r; asm("sqrt.approx.f32 %0, %1;" : "=f"(r) : "f"(x)); return r;
}

// blocks [0, NS)     : pv  (masked projected distance over ROI)  -- latency/BW bound
// blocks [NS, 2*NS)  : re/te/ad/pj (scalars + mesh reductions)   -- fma bound
__global__ __launch_bounds__(TPB, 2) void score_kernel(
    const int*   __restrict__ obj_id,
    const float* __restrict__ cam_K,
    const float* __restrict__ gtR,
    const float* __restrict__ gtT,
    const float* __restrict__ prR,
    const float* __restrict__ prT,
    const float* __restrict__ coord,        // [NS,3,H,W]
    const unsigned int* __restrict__ maskp, // [NS,H,W] nonzero == true
    const float* __restrict__ mesh,         // [NOBJ,MPTS,3]
    const float* __restrict__ diam,
    float*       __restrict__ out)          // [5,NS]
{
    const int tid  = threadIdx.x;
    const bool is_pv = (blockIdx.x < NS);
    const int n   = is_pv ? blockIdx.x : (blockIdx.x - NS);

    __shared__ u64 sdR[9], sdt[3];
    __shared__ float sInvDiam;
    __shared__ int   sObj;
    __shared__ float redA[8], redB[8];

    // ---- per-thread register coefficients (broadcast pairs) ----
    // Kp = K@Rp rows 0..2 ; Kg rows 0,1 NEGATED, row 2 positive.
    float K[9], Rp[9], Rg[9], tp[3], tg[3];
#pragma unroll
    for (int k = 0; k < 9; k++) {
        K[k]  = __ldg(cam_K + n * 9 + k);
        Rp[k] = __ldg(prR   + n * 9 + k);
        Rg[k] = __ldg(gtR   + n * 9 + k);
    }
#pragma unroll
    for (int k = 0; k < 3; k++) { tp[k] = __ldg(prT + n*3 + k); tg[k] = __ldg(gtT + n*3 + k); }

    u64 cKp[9], cKg[9], cktp[3], cktg[3];
#pragma unroll
    for (int i = 0; i < 3; i++) {
        float sg = (i < 2) ? -1.0f : 1.0f;   // negate Kg rows 0,1
#pragma unroll
        for (int j = 0; j < 3; j++) {
            float a = K[i*3+0]*Rp[0*3+j] + K[i*3+1]*Rp[1*3+j] + K[i*3+2]*Rp[2*3+j];
            float b = (K[i*3+0]*Rg[0*3+j] + K[i*3+1]*Rg[1*3+j] + K[i*3+2]*Rg[2*3+j]) * sg;
            cKp[i*3+j] = pk2(a, a);
            cKg[i*3+j] = pk2(b, b);
        }
        float a = K[i*3+0]*tp[0] + K[i*3+1]*tp[1] + K[i*3+2]*tp[2];
        float b = (K[i*3+0]*tg[0] + K[i*3+1]*tg[1] + K[i*3+2]*tg[2]) * sg;
        cktp[i] = pk2(a, a);
        cktg[i] = pk2(b, b);
    }

    if (!is_pv && tid == 0) {
#pragma unroll
        for (int k = 0; k < 9; k++) { float d = Rp[k] - Rg[k]; sdR[k] = pk2(d, d); }
#pragma unroll
        for (int k = 0; k < 3; k++) { float d = tp[k] - tg[k]; sdt[k] = pk2(d, d); }
        int obj = obj_id[n];
        sObj = obj;
        sInvDiam = 1.0f / diam[obj];
        float tr = 0.0f;
#pragma unroll
        for (int k = 0; k < 9; k++) tr += Rp[k] * Rg[k];
        float c = fminf(fmaxf(tr, -1.0f), 3.0f);
        out[n] = acosf((c - 1.0f) * 0.5f) * 57.2957795130823209f;
        float dx = tp[0]-tg[0], dy = tp[1]-tg[1], dz = tp[2]-tg[2];
        out[NS + n] = sqrtf(dx*dx + dy*dy + dz*dz) * 100.0f;
    }
    if (!is_pv) __syncthreads();

    float accA = 0.0f, accB = 0.0f;

    if (is_pv) {
        const float4* vx = (const float4*)(coord + (size_t)n * 3 * HW);
        const float4* vy = vx + HW4;
        const float4* vz = vy + HW4;
        const uint4*  mk = (const uint4*)(maskp + (size_t)n * HW);
        // HW4 = 4096 = 16 * TPB; stride 2*TPB -> 8 iterations, both lanes valid.
        for (int i = tid; i < HW4; i += 2 * TPB) {
            // front-batched loads: 8 independent LDG.128 in flight
            float4 X0 = __ldg(vx + i);
            float4 Y0 = __ldg(vy + i);
            float4 Z0 = __ldg(vz + i);
            uint4  M0 = __ldg(mk + i);
            float4 X1 = __ldg(vx + i + TPB);
            float4 Y1 = __ldg(vy + i + TPB);
            float4 Z1 = __ldg(vz + i + TPB);
            uint4  M1 = __ldg(mk + i + TPB);
#pragma unroll
            for (int u = 0; u < 2; u++) {
                float4 X = u ? X1 : X0;
                float4 Y = u ? Y1 : Y0;
                float4 Z = u ? Z1 : Z0;
                uint4  Mw = u ? M1 : M0;
#pragma unroll
                for (int half = 0; half < 2; half++) {
                    u64 x2 = half ? pk2(X.z, X.w) : pk2(X.x, X.y);
                    u64 y2 = half ? pk2(Y.z, Y.w) : pk2(Y.x, Y.y);
                    u64 z2 = half ? pk2(Z.z, Z.w) : pk2(Z.x, Z.y);
                    unsigned int m0 = half ? Mw.z : Mw.x;
                    unsigned int m1 = half ? Mw.w : Mw.y;

                    u64 hx  = fma2(cKp[0], x2, fma2(cKp[1], y2, fma2(cKp[2], z2, cktp[0])));
                    u64 hy  = fma2(cKp[3], x2, fma2(cKp[4], y2, fma2(cKp[5], z2, cktp[1])));
                    u64 hz  = fma2(cKp[6], x2, fma2(cKp[7], y2, fma2(cKp[8], z2, cktp[2])));
                    u64 gxn = fma2(cKg[0], x2, fma2(cKg[1], y2, fma2(cKg[2], z2, cktg[0])));
                    u64 gyn = fma2(cKg[3], x2, fma2(cKg[4], y2, fma2(cKg[5], z2, cktg[1])));
                    u64 gz  = fma2(cKg[6], x2, fma2(cKg[7], y2, fma2(cKg[8], z2, cktg[2])));

                    u64 nx = fma2(gxn, hz, mul2(hx, gz));   // hx*gz - gx*hz
                    u64 ny = fma2(gyn, hz, mul2(hy, gz));
                    u64 dn = mul2(hz, gz);
                    float dn0, dn1;
                    upk2(dn, dn0, dn1);
                    u64 r2 = pk2(rcpa(dn0), rcpa(dn1));
                    u64 s2 = mul2(fma2(ny, ny, mul2(nx, nx)), mul2(r2, r2));
                    float s0, s1;
                    upk2(s2, s0, s1);
                    if (m0 != 0u) { accA += sqrta(s0); accB += 1.0f; }
                    if (m1 != 0u) { accA += sqrta(s1); accB += 1.0f; }
                }
            }
        }
    } else {
        const float2* pts2 = (const float2*)(mesh + (size_t)sObj * MPTS * 3);
        // MPTS/2 = 4096 = 16 * TPB; stride 2*TPB, both lanes valid.
        for (int t = tid; t < MPTS / 2; t += 2 * TPB) {
            float2 a0 = __ldg(pts2 + 3*t + 0);
            float2 b0 = __ldg(pts2 + 3*t + 1);
            float2 c0 = __ldg(pts2 + 3*t + 2);
            float2 a1 = __ldg(pts2 + 3*(t + TPB) + 0);
            float2 b1 = __ldg(pts2 + 3*(t + TPB) + 1);
            float2 c1 = __ldg(pts2 + 3*(t + TPB) + 2);
#pragma unroll
            for (int u = 0; u < 2; u++) {
                float2 a = u ? a1 : a0;
                float2 b = u ? b1 : b0;
                float2 c = u ? c1 : c0;
                u64 px2 = pk2(a.x, b.y);
                u64 py2 = pk2(a.y, c.x);
                u64 pz2 = pk2(b.x, c.y);

                // ADD
                u64 ax = fma2(sdR[0], px2, fma2(sdR[1], py2, fma2(sdR[2], pz2, sdt[0])));
                u64 ay = fma2(sdR[3], px2, fma2(sdR[4], py2, fma2(sdR[5], pz2, sdt[1])));
                u64 az = fma2(sdR[6], px2, fma2(sdR[7], py2, fma2(sdR[8], pz2, sdt[2])));
                u64 sa = fma2(az, az, fma2(ay, ay, mul2(ax, ax)));
                float sa0, sa1;
                upk2(sa, sa0, sa1);
                accA += sqrta(sa0) + sqrta(sa1);

                // PROJ
                u64 hx  = fma2(cKp[0], px2, fma2(cKp[1], py2, fma2(cKp[2], pz2, cktp[0])));
                u64 hy  = fma2(cKp[3], px2, fma2(cKp[4], py2, fma2(cKp[5], pz2, cktp[1])));
                u64 hz  = fma2(cKp[6], px2, fma2(cKp[7], py2, fma2(cKp[8], pz2, cktp[2])));
                u64 gxn = fma2(cKg[0], px2, fma2(cKg[1], py2, fma2(cKg[2], pz2, cktg[0])));
                u64 gyn = fma2(cKg[3], px2, fma2(cKg[4], py2, fma2(cKg[5], pz2, cktg[1])));
                u64 gz  = fma2(cKg[6], px2, fma2(cKg[7], py2, fma2(cKg[8], pz2, cktg[2])));

                u64 nx = fma2(gxn, hz, mul2(hx, gz));
                u64 ny = fma2(gyn, hz, mul2(hy, gz));
                u64 dn = mul2(hz, gz);
                float dn0, dn1;
                upk2(dn, dn0, dn1);
                u64 r2 = pk2(rcpa(dn0), rcpa(dn1));
                u64 sp = mul2(fma2(ny, ny, mul2(nx, nx)), mul2(r2, r2));
                float sp0, sp1;
                upk2(sp, sp0, sp1);
                accB += sqrta(sp0) + sqrta(sp1);
            }
        }
    }

    // block reduce (accA, accB)
    {
        const int lane = tid & 31;
        const int wid  = tid >> 5;
#pragma unroll
        for (int o = 16; o > 0; o >>= 1) {
            accA += __shfl_down_sync(0xffffffffu, accA, o);
            accB += __shfl_down_sync(0xffffffffu, accB, o);
        }
        if (lane == 0) { redA[wid] = accA; redB[wid] = accB; }
        __syncthreads();
        if (wid == 0) {
            accA = (lane < (TPB / 32)) ? redA[lane] : 0.0f;
            accB = (lane < (TPB / 32)) ? redB[lane] : 0.0f;
#pragma unroll
            for (int o = 4; o > 0; o >>= 1) {
                accA += __shfl_down_sync(0xffffffffu, accA, o);
                accB += __shfl_down_sync(0xffffffffu, accB, o);
            }
            if (lane == 0) {
                if (is_pv) {
                    out[4 * NS + n] = accA / fmaxf(accB, 1.0f);
                } else {
                    out[2 * NS + n] = accA * (1.0f / MPTS) * sInvDiam;
                    out[3 * NS + n] = accB * (1.0f / MPTS);
                }
            }
        }
    }
}

extern "C" void kernel_launch(void* const* d_in, const int* in_sizes, int n_in,
                              void* d_out, int out_size) {
    const int*   obj_id = (const int*)  d_in[0];
    const float* cam_K  = (const float*)d_in[1];
    const float* gtR    = (const float*)d_in[2];
    const float* gtT    = (const float*)d_in[3];
    const float* prR    = (const float*)d_in[4];
    const float* prT    = (const float*)d_in[5];
    const float* coord  = (const float*)d_in[6];
    const unsigned int* maskp = (const unsigned int*)d_in[7];
    const float* mesh   = (const float*)d_in[8];
    const float* diam   = (const float*)d_in[9];
    float* out = (float*)d_out;

    score_kernel<<<2 * NS, TPB>>>(obj_id, cam_K, gtR, gtT, prR, prT,
                                  coord, maskp, mesh, diam, out);
}